// round 2
// baseline (speedup 1.0000x reference)
#include <cuda_runtime.h>
#include <math.h>

#define NN 4096
#define EE 131072
#define DD 512
#define HHH 512
#define OUTC 64
#define NWRD 128   // 4096 bits / 32

// ---------------- scratch (device globals; no allocations) ----------------
__device__ unsigned g_Abits[NN * NWRD];
__device__ unsigned g_Rbits[NN * NWRD];
__device__ int g_src[EE], g_dst[EE];
__device__ int g_is64;
__device__ int g_deg_src[NN], g_deg_dst[NN];
__device__ int g_off_src[NN + 1], g_off_dst[NN + 1];
__device__ int g_cur_src[NN], g_cur_dst[NN];
__device__ int g_csr_src[EE], g_csr_dst[EE];
__device__ float g_inv[NN];
__device__ float g_cose[EE];
__device__ float g_segm[NN], g_segd[NN];
__device__ float g_ego[NN * DD], g_cut[NN * DD], g_cosf[NN * DD];
__device__ float g_aggE[NN * DD], g_aggC[NN * DD], g_aggS[NN * DD];
__device__ float g_comb[NN * 4 * HHH];
__device__ float g_logits[NN * OUTC];

// ---------------- setup kernels ----------------

__global__ void k_zero() {
    int idx = blockIdx.x * blockDim.x + threadIdx.x;
    for (int i = idx; i < NN * NWRD; i += gridDim.x * blockDim.x) g_Abits[i] = 0u;
    if (idx < NN) {
        g_deg_src[idx] = 0; g_deg_dst[idx] = 0;
        g_cur_src[idx] = 0; g_cur_dst[idx] = 0;
    }
}

// detect whether edge_index buffer is int64 (odd 32-bit words all zero) or int32
__global__ void k_detect(const unsigned* __restrict__ raw) {
    __shared__ unsigned red[256];
    int t = threadIdx.x;
    red[t] = raw[2 * t + 1];
    __syncthreads();
    for (int d = 128; d > 0; d >>= 1) {
        if (t < d) red[t] |= red[t + d];
        __syncthreads();
    }
    if (t == 0) g_is64 = (red[0] == 0u) ? 1 : 0;
}

__global__ void k_convert(const unsigned* __restrict__ raw) {
    int e = blockIdx.x * blockDim.x + threadIdx.x;
    if (e >= EE) return;
    if (g_is64) {
        g_src[e] = (int)raw[2 * e];
        g_dst[e] = (int)raw[2 * (EE + e)];
    } else {
        g_src[e] = (int)raw[e];
        g_dst[e] = (int)raw[EE + e];
    }
}

// inv_norm per node: 1 / max(||x_i||, 1e-12)
__global__ void k_norm(const float* __restrict__ x) {
    int i = blockIdx.x, t = threadIdx.x;  // 128 threads
    __shared__ float red[128];
    float s = 0.f;
#pragma unroll
    for (int j = 0; j < 4; j++) {
        float v = x[i * DD + t + j * 128];
        s += v * v;
    }
    red[t] = s; __syncthreads();
    for (int d = 64; d > 0; d >>= 1) {
        if (t < d) red[t] += red[t + d];
        __syncthreads();
    }
    if (t == 0) g_inv[i] = 1.f / fmaxf(sqrtf(red[0]), 1e-12f);
}

// edge scatter: adjacency bitmask + degree counts
__global__ void k_edge() {
    int e = blockIdx.x * blockDim.x + threadIdx.x;
    if (e >= EE) return;
    int s = g_src[e], d = g_dst[e];
    atomicOr(&g_Abits[d * NWRD + (s >> 5)], 1u << (s & 31));
    atomicAdd(&g_deg_src[s], 1);
    atomicAdd(&g_deg_dst[d], 1);
}

// exclusive scan of 4096 ints -> off[0..4096]
__global__ void k_scan(const int* __restrict__ deg, int* __restrict__ off) {
    __shared__ int s[1024];
    int t = threadIdx.x;
    int v0 = deg[4 * t + 0], v1 = deg[4 * t + 1], v2 = deg[4 * t + 2], v3 = deg[4 * t + 3];
    int p1 = v0, p2 = v0 + v1, p3 = v0 + v1 + v2;
    int sum = p3 + v3;
    s[t] = sum; __syncthreads();
    for (int d = 1; d < 1024; d <<= 1) {
        int x = (t >= d) ? s[t - d] : 0;
        __syncthreads();
        s[t] += x;
        __syncthreads();
    }
    int base = s[t] - sum;  // exclusive
    off[4 * t + 0] = base;
    off[4 * t + 1] = base + p1;
    off[4 * t + 2] = base + p2;
    off[4 * t + 3] = base + p3;
    if (t == 1023) off[NN] = s[1023];
}

__global__ void k_fill() {
    int e = blockIdx.x * blockDim.x + threadIdx.x;
    if (e >= EE) return;
    int s = g_src[e];
    int p = atomicAdd(&g_cur_src[s], 1);
    g_csr_src[g_off_src[s] + p] = e;
    int d = g_dst[e];
    p = atomicAdd(&g_cur_dst[d], 1);
    g_csr_dst[g_off_dst[d] + p] = e;
}

// 2-hop boolean reachability rows: R_i = {i} | A_i | OR_{j in A_i} A_j
__global__ void k_rbits() {
    int i = blockIdx.x, t = threadIdx.x;  // 128 threads
    __shared__ unsigned short list[4096];
    __shared__ int sc[128];
    unsigned w = g_Abits[i * NWRD + t];
    int pc = __popc(w);
    sc[t] = pc; __syncthreads();
    for (int d = 1; d < 128; d <<= 1) {
        int v = (t >= d) ? sc[t - d] : 0;
        __syncthreads();
        sc[t] += v;
        __syncthreads();
    }
    int total = sc[127];
    int o = sc[t] - pc;
    unsigned ww = w;
    while (ww) {
        int b = __ffs((int)ww) - 1;
        list[o++] = (unsigned short)(t * 32 + b);
        ww &= ww - 1;
    }
    __syncthreads();
    unsigned r = w;
    if (t == (i >> 5)) r |= 1u << (i & 31);
    for (int l = 0; l < total; l++) {
        int j = (int)list[l];
        r |= g_Abits[j * NWRD + t];
    }
    g_Rbits[i * NWRD + t] = r;
}

// ego features: mean of x over reachability set
__global__ void k_ego(const float* __restrict__ x) {
    int i = blockIdx.x, t = threadIdx.x;  // 256 threads
    __shared__ unsigned short list[4096];
    __shared__ int sc[128];
    __shared__ int s_total;
    if (t < 128) sc[t] = __popc(g_Rbits[i * NWRD + t]);
    __syncthreads();
    for (int d = 1; d < 128; d <<= 1) {
        int v = 0;
        if (t < 128 && t >= d) v = sc[t - d];
        __syncthreads();
        if (t < 128) sc[t] += v;
        __syncthreads();
    }
    if (t < 128) {
        unsigned w = g_Rbits[i * NWRD + t];
        int o = sc[t] - __popc(w);
        while (w) {
            int b = __ffs((int)w) - 1;
            list[o++] = (unsigned short)(t * 32 + b);
            w &= w - 1;
        }
        if (t == 127) s_total = sc[127];
    }
    __syncthreads();
    int total = s_total;
    float a0 = 0.f, a1 = 0.f;
    int l = 0;
    for (; l + 4 <= total; l += 4) {
        int k0 = (int)list[l], k1 = (int)list[l + 1], k2 = (int)list[l + 2], k3 = (int)list[l + 3];
        a0 += x[k0 * DD + t];       a1 += x[k0 * DD + t + 256];
        a0 += x[k1 * DD + t];       a1 += x[k1 * DD + t + 256];
        a0 += x[k2 * DD + t];       a1 += x[k2 * DD + t + 256];
        a0 += x[k3 * DD + t];       a1 += x[k3 * DD + t + 256];
    }
    for (; l < total; l++) {
        int k = (int)list[l];
        a0 += x[k * DD + t];
        a1 += x[k * DD + t + 256];
    }
    float inv = 1.f / (float)total;
    g_ego[i * DD + t] = a0 * inv;
    g_ego[i * DD + t + 256] = a1 * inv;
}

// cut features: weighted mean of x[dst] over out-edges
__global__ void k_cut(const float* __restrict__ x, const float* __restrict__ wgt) {
    int i = blockIdx.x, t = threadIdx.x;  // 128
    int beg = g_off_src[i];
    int deg = g_off_src[i + 1] - beg;
    __shared__ float red[128];
    float wp = 0.f;
    for (int l = t; l < deg; l += 128) wp += wgt[g_csr_src[beg + l]];
    red[t] = wp; __syncthreads();
    for (int d = 64; d > 0; d >>= 1) {
        if (t < d) red[t] += red[t + d];
        __syncthreads();
    }
    float wsum = red[0];
    __syncthreads();
    __shared__ int sd[128];
    __shared__ float sw[128];
    float a[4] = {0.f, 0.f, 0.f, 0.f};
    for (int base = 0; base < deg; base += 128) {
        int l = base + t;
        if (l < deg) {
            int e = g_csr_src[beg + l];
            sd[t] = g_dst[e];
            sw[t] = wgt[e];
        }
        __syncthreads();
        int lim = min(128, deg - base);
        for (int u = 0; u < lim; u++) {
            const float* xr = x + sd[u] * DD;
            float ww = sw[u];
            a[0] += ww * xr[t];
            a[1] += ww * xr[t + 128];
            a[2] += ww * xr[t + 256];
            a[3] += ww * xr[t + 384];
        }
        __syncthreads();
    }
    bool use = (deg > 0) && (wsum > 0.f);
    float inv = use ? 1.f / wsum : 0.f;
#pragma unroll
    for (int c = 0; c < 4; c++) {
        int col = t + c * 128;
        g_cut[i * DD + col] = use ? a[c] * inv : x[i * DD + col];
    }
}

// per-edge cosine similarity
__global__ void k_cos_edge(const float* __restrict__ x) {
    int e = blockIdx.x * 8 + (threadIdx.x >> 5);
    int lane = threadIdx.x & 31;
    int s = g_src[e], d = g_dst[e];
    const float* xs = x + s * DD;
    const float* xd = x + d * DD;
    float acc = 0.f;
#pragma unroll
    for (int u = 0; u < 16; u++) acc += xs[lane + 32 * u] * xd[lane + 32 * u];
    for (int o = 16; o > 0; o >>= 1) acc += __shfl_xor_sync(0xffffffffu, acc, o);
    if (lane == 0) g_cose[e] = acc * g_inv[s] * g_inv[d];
}

// segment max + sum(exp) over out-edges
__global__ void k_cos_node() {
    int i = blockIdx.x, t = threadIdx.x;  // 128
    int beg = g_off_src[i];
    int deg = g_off_src[i + 1] - beg;
    __shared__ float red[128];
    float mx = -1e30f;
    for (int l = t; l < deg; l += 128) mx = fmaxf(mx, g_cose[g_csr_src[beg + l]]);
    red[t] = mx; __syncthreads();
    for (int d = 64; d > 0; d >>= 1) {
        if (t < d) red[t] = fmaxf(red[t], red[t + d]);
        __syncthreads();
    }
    float m = red[0];
    __syncthreads();
    float sp = 0.f;
    for (int l = t; l < deg; l += 128) sp += expf(g_cose[g_csr_src[beg + l]] - m);
    red[t] = sp; __syncthreads();
    for (int d = 64; d > 0; d >>= 1) {
        if (t < d) red[t] += red[t + d];
        __syncthreads();
    }
    if (t == 0) {
        g_segm[i] = (deg > 0) ? m : 0.f;
        g_segd[i] = (deg > 0) ? red[0] : 0.f;
    }
}

// softmax-weighted mean of x[dst] over out-edges
__global__ void k_cosf(const float* __restrict__ x) {
    int i = blockIdx.x, t = threadIdx.x;  // 128
    int beg = g_off_src[i];
    int deg = g_off_src[i + 1] - beg;
    float m = g_segm[i];
    float den = g_segd[i];
    float dsafe = (den > 0.f) ? den : 1.f;
    __shared__ int sd[128];
    __shared__ float sw[128];
    float a[4] = {0.f, 0.f, 0.f, 0.f};
    float tot = 0.f;
    for (int base = 0; base < deg; base += 128) {
        int l = base + t;
        if (l < deg) {
            int e = g_csr_src[beg + l];
            sd[t] = g_dst[e];
            sw[t] = expf(g_cose[e] - m) / dsafe;
        }
        __syncthreads();
        int lim = min(128, deg - base);
        for (int u = 0; u < lim; u++) {
            const float* xr = x + sd[u] * DD;
            float ww = sw[u];
            tot += ww;
            a[0] += ww * xr[t];
            a[1] += ww * xr[t + 128];
            a[2] += ww * xr[t + 256];
            a[3] += ww * xr[t + 384];
        }
        __syncthreads();
    }
    float tsafe = (tot > 0.f) ? tot : 1.f;
#pragma unroll
    for (int c = 0; c < 4; c++) {
        int col = t + c * 128;
        g_cosf[i * DD + col] = (deg > 0) ? a[c] / tsafe : x[i * DD + col];
    }
}

// fused aggregation over in-edges for all three feature matrices
__global__ void k_agg3() {
    int i = blockIdx.x, t = threadIdx.x;  // 128
    int beg = g_off_dst[i];
    int deg = g_off_dst[i + 1] - beg;
    __shared__ int ss[128];
    float aE[4] = {0.f, 0.f, 0.f, 0.f};
    float aC[4] = {0.f, 0.f, 0.f, 0.f};
    float aS[4] = {0.f, 0.f, 0.f, 0.f};
    for (int base = 0; base < deg; base += 128) {
        int l = base + t;
        if (l < deg) ss[t] = g_src[g_csr_dst[beg + l]];
        __syncthreads();
        int lim = min(128, deg - base);
        for (int u = 0; u < lim; u++) {
            int b = ss[u] * DD;
#pragma unroll
            for (int c = 0; c < 4; c++) {
                int col = t + c * 128;
                aE[c] += g_ego[b + col];
                aC[c] += g_cut[b + col];
                aS[c] += g_cosf[b + col];
            }
        }
        __syncthreads();
    }
#pragma unroll
    for (int c = 0; c < 4; c++) {
        int col = t + c * 128;
        g_aggE[i * DD + col] = aE[c];
        g_aggC[i * DD + col] = aC[c];
        g_aggS[i * DD + col] = aS[c];
    }
}

// generic fp32 GEMM: C[row*ldc+col] = op(A[row*lda + k] @ W[k*ldw + col] + scale*b[col])
// tiles 64x64x16, 256 threads, 4x4 per thread
__global__ void k_gemm(const float* __restrict__ A, int lda,
                       const float* __restrict__ W, int ldw,
                       const float* __restrict__ bias,
                       float* __restrict__ C, int ldc,
                       int K, const int* __restrict__ deg, int relu) {
    __shared__ float As[16][65];
    __shared__ float Ws[16][65];
    int tid = threadIdx.x;
    int tx = tid & 15, ty = tid >> 4;
    int br = blockIdx.y * 64, bc = blockIdx.x * 64;
    float acc[4][4];
#pragma unroll
    for (int r = 0; r < 4; r++)
#pragma unroll
        for (int c = 0; c < 4; c++) acc[r][c] = 0.f;

    for (int kb = 0; kb < K; kb += 16) {
#pragma unroll
        for (int r = 0; r < 4; r++) {
            int idx = tid + r * 256;
            int m = idx >> 4, k = idx & 15;
            As[k][m] = A[(br + m) * lda + kb + k];
        }
#pragma unroll
        for (int r = 0; r < 4; r++) {
            int idx = tid + r * 256;
            int k = idx >> 6, n = idx & 63;
            Ws[k][n] = W[(kb + k) * ldw + bc + n];
        }
        __syncthreads();
#pragma unroll
        for (int k = 0; k < 16; k++) {
            float a[4], w[4];
#pragma unroll
            for (int r = 0; r < 4; r++) a[r] = As[k][ty * 4 + r];
#pragma unroll
            for (int c = 0; c < 4; c++) w[c] = Ws[k][tx * 4 + c];
#pragma unroll
            for (int r = 0; r < 4; r++)
#pragma unroll
                for (int c = 0; c < 4; c++) acc[r][c] += a[r] * w[c];
        }
        __syncthreads();
    }
#pragma unroll
    for (int r = 0; r < 4; r++) {
        int row = br + ty * 4 + r;
        float sc = deg ? (float)deg[row] : 1.f;
#pragma unroll
        for (int c = 0; c < 4; c++) {
            int col = bc + tx * 4 + c;
            float v = acc[r][c] + sc * bias[col];
            if (relu) v = fmaxf(v, 0.f);
            C[row * ldc + col] = v;
        }
    }
}

// row-wise log_softmax over 64 logits; warp per row
__global__ void k_lsm(float* __restrict__ out) {
    int row = blockIdx.x * 4 + (threadIdx.x >> 5);
    int lane = threadIdx.x & 31;
    float v0 = g_logits[row * OUTC + lane];
    float v1 = g_logits[row * OUTC + 32 + lane];
    float m = fmaxf(v0, v1);
    for (int o = 16; o > 0; o >>= 1) m = fmaxf(m, __shfl_xor_sync(0xffffffffu, m, o));
    float s = expf(v0 - m) + expf(v1 - m);
    for (int o = 16; o > 0; o >>= 1) s += __shfl_xor_sync(0xffffffffu, s, o);
    float l = m + logf(s);
    out[row * OUTC + lane] = v0 - l;
    out[row * OUTC + 32 + lane] = v1 - l;
}

// ---------------- launcher ----------------
extern "C" void kernel_launch(void* const* d_in, const int* in_sizes, int n_in,
                              void* d_out, int out_size) {
    const float* x      = (const float*)d_in[0];
    const unsigned* raw = (const unsigned*)d_in[1];
    const float* ew     = (const float*)d_in[2];
    const float* W_ego  = (const float*)d_in[3];
    const float* b_ego  = (const float*)d_in[4];
    const float* W_cut  = (const float*)d_in[5];
    const float* b_cut  = (const float*)d_in[6];
    const float* W_cos  = (const float*)d_in[7];
    const float* b_cos  = (const float*)d_in[8];
    const float* W_glob = (const float*)d_in[9];
    const float* b_glob = (const float*)d_in[10];
    const float* W_fc   = (const float*)d_in[11];
    const float* b_fc   = (const float*)d_in[12];
    float* out = (float*)d_out;

    float *p_aggE, *p_aggC, *p_aggS, *p_comb, *p_logits;
    int* p_degdst;
    cudaGetSymbolAddress((void**)&p_aggE, g_aggE);
    cudaGetSymbolAddress((void**)&p_aggC, g_aggC);
    cudaGetSymbolAddress((void**)&p_aggS, g_aggS);
    cudaGetSymbolAddress((void**)&p_comb, g_comb);
    cudaGetSymbolAddress((void**)&p_logits, g_logits);
    cudaGetSymbolAddress((void**)&p_degdst, g_deg_dst);
    int *p_degsrc, *p_offsrc, *p_offdst;
    cudaGetSymbolAddress((void**)&p_degsrc, g_deg_src);
    cudaGetSymbolAddress((void**)&p_offsrc, g_off_src);
    cudaGetSymbolAddress((void**)&p_offdst, g_off_dst);

    k_zero<<<512, 1024>>>();
    k_detect<<<1, 256>>>(raw);
    k_convert<<<EE / 256, 256>>>(raw);
    k_norm<<<NN, 128>>>(x);
    k_edge<<<EE / 256, 256>>>();
    k_scan<<<1, 1024>>>(p_degsrc, p_offsrc);
    k_scan<<<1, 1024>>>(p_degdst, p_offdst);
    k_fill<<<EE / 256, 256>>>();
    k_rbits<<<NN, 128>>>();
    k_ego<<<NN, 256>>>(x);
    k_cut<<<NN, 128>>>(x, ew);
    k_cos_edge<<<EE / 8, 256>>>(x);
    k_cos_node<<<NN, 128>>>();
    k_cosf<<<NN, 128>>>(x);
    k_agg3<<<NN, 128>>>();

    // enc_f = relu(agg_f @ W_f + deg_in * b_f)  -> comb columns [f*512, f*512+512)
    k_gemm<<<dim3(HHH / 64, NN / 64), 256>>>(p_aggE, DD, W_ego, HHH, b_ego,
                                             p_comb + 0 * HHH, 4 * HHH, DD, p_degdst, 1);
    k_gemm<<<dim3(HHH / 64, NN / 64), 256>>>(p_aggC, DD, W_cut, HHH, b_cut,
                                             p_comb + 1 * HHH, 4 * HHH, DD, p_degdst, 1);
    k_gemm<<<dim3(HHH / 64, NN / 64), 256>>>(p_aggS, DD, W_cos, HHH, b_cos,
                                             p_comb + 2 * HHH, 4 * HHH, DD, p_degdst, 1);
    // glob = x @ W_glob + b_glob (no relu)
    k_gemm<<<dim3(HHH / 64, NN / 64), 256>>>(x, DD, W_glob, HHH, b_glob,
                                             p_comb + 3 * HHH, 4 * HHH, DD, (const int*)0, 0);
    // logits = comb @ W_fc + b_fc
    k_gemm<<<dim3(OUTC / 64, NN / 64), 256>>>(p_comb, 4 * HHH, W_fc, OUTC, b_fc,
                                              p_logits, OUTC, 4 * HHH, (const int*)0, 0);
    k_lsm<<<NN / 4, 128>>>(out);

    (void)in_sizes; (void)n_in; (void)out_size; (void)ew;
}